// round 3
// baseline (speedup 1.0000x reference)
#include <cuda_runtime.h>
#include <cuda_bf16.h>
#include <math.h>

#define HW   65536
#define IMG  256
#define BATCH 4
#define CH   192
#define HEADS 8
#define HD   24

// ---------------- scratch (device globals; no runtime allocation) ----------------
__device__ float g_qkv[(long)BATCH * 576 * HW];   // after 1x1 conv   (604 MB)
__device__ float g_dw [(long)BATCH * 576 * HW];   // after dw 3x3     (604 MB)
__device__ float g_S  [BATCH * HEADS * HD * HD];  // raw gram q.k^T
__device__ float g_ssq[2 * BATCH * HEADS * HD];   // sumsq q (first 768), sumsq k
__device__ float g_W  [BATCH * CH * CH];          // proj_w folded with attn

// ---------------- zero accumulators (must be per-call for graph replay) ----------
__global__ void zero_kernel()
{
    int i = blockIdx.x * blockDim.x + threadIdx.x;
    if (i < BATCH * HEADS * HD * HD) g_S[i] = 0.f;
    if (i < 2 * BATCH * HEADS * HD)  g_ssq[i] = 0.f;
}

// ---------------- SGEMM: C[M x 65536] = A[M x K] * B[K x 65536], batched ---------
// tile 64(M) x 128(N) x 16(K), 256 threads, 4x8 per thread
__global__ __launch_bounds__(256) void sgemm_kernel(
    const float* __restrict__ A, long aStride,
    const float* __restrict__ B, long bStride,
    float* __restrict__ C, long cStride,
    int M, int K)
{
    const int bz = blockIdx.z;
    const float* Ab = A + (long)bz * aStride;
    const float* Bb = B + (long)bz * bStride;
    float*       Cb = C + (long)bz * cStride;
    const int bm = blockIdx.y * 64;
    const int bn = blockIdx.x * 128;

    __shared__ float As[16][68];   // [k][m], padded
    __shared__ float Bs[16][132];  // [k][n], padded

    const int tid = threadIdx.x;
    const int ty = tid >> 4;          // 0..15 -> rows ty*4..+3
    const int tx = tid & 15;          // 0..15 -> cols tx*8..+7

    const int arow = tid >> 2;        // 0..63
    const int ak   = (tid & 3) << 2;  // 0,4,8,12
    const int brow = tid >> 4;        // 0..15
    const int bcol = (tid & 15) << 3; // 0..120

    float acc[4][8];
#pragma unroll
    for (int i = 0; i < 4; i++)
#pragma unroll
        for (int j = 0; j < 8; j++) acc[i][j] = 0.f;

    for (int k0 = 0; k0 < K; k0 += 16) {
        float4 av = *reinterpret_cast<const float4*>(Ab + (long)(bm + arow) * K + k0 + ak);
        As[ak + 0][arow] = av.x;
        As[ak + 1][arow] = av.y;
        As[ak + 2][arow] = av.z;
        As[ak + 3][arow] = av.w;
        const float* bp = Bb + (long)(k0 + brow) * HW + bn + bcol;
        float4 bv0 = *reinterpret_cast<const float4*>(bp);
        float4 bv1 = *reinterpret_cast<const float4*>(bp + 4);
        *reinterpret_cast<float4*>(&Bs[brow][bcol])     = bv0;
        *reinterpret_cast<float4*>(&Bs[brow][bcol + 4]) = bv1;
        __syncthreads();
#pragma unroll
        for (int kk = 0; kk < 16; kk++) {
            float4 a  = *reinterpret_cast<const float4*>(&As[kk][ty << 2]);
            float4 b0 = *reinterpret_cast<const float4*>(&Bs[kk][tx << 3]);
            float4 b1 = *reinterpret_cast<const float4*>(&Bs[kk][(tx << 3) + 4]);
            float av4[4] = {a.x, a.y, a.z, a.w};
            float bv8[8] = {b0.x, b0.y, b0.z, b0.w, b1.x, b1.y, b1.z, b1.w};
#pragma unroll
            for (int i = 0; i < 4; i++)
#pragma unroll
                for (int j = 0; j < 8; j++)
                    acc[i][j] += av4[i] * bv8[j];
        }
        __syncthreads();
    }
#pragma unroll
    for (int i = 0; i < 4; i++) {
        float* cp = Cb + (long)(bm + (ty << 2) + i) * HW + bn + (tx << 3);
        *reinterpret_cast<float4*>(cp)     = make_float4(acc[i][0], acc[i][1], acc[i][2], acc[i][3]);
        *reinterpret_cast<float4*>(cp + 4) = make_float4(acc[i][4], acc[i][5], acc[i][6], acc[i][7]);
    }
}

// ---------------- depthwise 3x3 conv, pad 1 (cross-correlation, per channel) -----
__global__ __launch_bounds__(256) void dwconv_kernel(const float* __restrict__ in,
                                                     const float* __restrict__ w)
{
    const int ch = blockIdx.y;   // 0..575
    const int b  = blockIdx.z;
    const long base = ((long)b * 576 + ch) * HW;
    const float* ip = in + base;
    float* op = g_dw + base;

    float w9[9];
#pragma unroll
    for (int i = 0; i < 9; i++) w9[i] = __ldg(&w[ch * 9 + i]);

    __shared__ float s[10][258];
    const int t = threadIdx.x;          // 0..255 = image column
    const int r0 = blockIdx.x * 8;      // 8 output rows per block
#pragma unroll
    for (int rr = 0; rr < 10; rr++) {
        int r = r0 - 1 + rr;
        s[rr][t + 1] = (r >= 0 && r < IMG) ? ip[r * IMG + t] : 0.f;
    }
    if (t < 10) { s[t][0] = 0.f; s[t][257] = 0.f; }
    __syncthreads();
#pragma unroll
    for (int rr = 0; rr < 8; rr++) {
        float acc = 0.f;
#pragma unroll
        for (int ky = 0; ky < 3; ky++)
#pragma unroll
            for (int kx = 0; kx < 3; kx++)
                acc += s[rr + ky][t + kx] * w9[ky * 3 + kx];
        op[(r0 + rr) * IMG + t] = acc;
    }
}

// ---------------- per-(b,h): Sraw = q k^T over HW, plus sumsq rows ---------------
// grid (64 n-blocks, 8 heads, 4 batch), 288 threads = 8 n-groups x (6x6) 4x4 tiles
__global__ __launch_bounds__(288) void qk_gram_kernel()
{
    const int b = blockIdx.z, h = blockIdx.y;
    const int bh = b * HEADS + h;
    const float* Q  = g_dw + ((long)b * 576 + h * HD) * HW;
    const float* Kp = g_dw + ((long)b * 576 + CH + h * HD) * HW;

    __shared__ float qs[HD][129];
    __shared__ float ks[HD][129];
    __shared__ float red[8 * 576];

    const int tid = threadIdx.x;
    const int g = tid / 36;
    const int p = tid % 36;
    const int d0 = (p % 6) * 4;
    const int e0 = (p / 6) * 4;

    float acc[4][4];
#pragma unroll
    for (int i = 0; i < 4; i++)
#pragma unroll
        for (int j = 0; j < 4; j++) acc[i][j] = 0.f;
    float sq = 0.f;

    for (int c = 0; c < 8; c++) {
        const long n0 = ((long)blockIdx.x * 8 + c) * 128;
        for (int idx = tid; idx < HD * 128; idx += 288) {
            int r = idx >> 7, cc = idx & 127;
            qs[r][cc] = Q[(long)r * HW + n0 + cc];
            ks[r][cc] = Kp[(long)r * HW + n0 + cc];
        }
        __syncthreads();
        const int nbeg = g * 16;
#pragma unroll 4
        for (int nn = nbeg; nn < nbeg + 16; nn++) {
            float qv[4], kv[4];
#pragma unroll
            for (int i = 0; i < 4; i++) { qv[i] = qs[d0 + i][nn]; kv[i] = ks[e0 + i][nn]; }
#pragma unroll
            for (int i = 0; i < 4; i++)
#pragma unroll
                for (int j = 0; j < 4; j++)
                    acc[i][j] += qv[i] * kv[j];
        }
        if (tid < HD) {
            for (int cc = 0; cc < 128; cc++) { float v = qs[tid][cc]; sq += v * v; }
        } else if (tid < 2 * HD) {
            for (int cc = 0; cc < 128; cc++) { float v = ks[tid - HD][cc]; sq += v * v; }
        }
        __syncthreads();
    }
#pragma unroll
    for (int i = 0; i < 4; i++)
#pragma unroll
        for (int j = 0; j < 4; j++)
            red[g * 576 + p * 16 + i * 4 + j] = acc[i][j];
    __syncthreads();
    for (int t = tid; t < 576; t += 288) {
        float s = 0.f;
#pragma unroll
        for (int gg = 0; gg < 8; gg++) s += red[gg * 576 + t];
        int p2 = t >> 4, idx = t & 15;
        int d = (p2 % 6) * 4 + (idx >> 2);
        int e = (p2 / 6) * 4 + (idx & 3);
        atomicAdd(&g_S[((long)bh * HD + d) * HD + e], s);
    }
    if (tid < 2 * HD) {
        int off = (tid < HD) ? (bh * HD + tid) : (BATCH * HEADS * HD + bh * HD + (tid - HD));
        atomicAdd(&g_ssq[off], sq);
    }
}

// ---------------- normalize + softmax + fold attn into proj_w -> W[b] ------------
__global__ __launch_bounds__(576) void combine_kernel(const float* __restrict__ proj_w,
                                                      const float* __restrict__ temp)
{
    const int bh = blockIdx.x;
    const int b = bh >> 3, h = bh & 7;
    __shared__ float attn[HD][HD];
    __shared__ float nq[HD], nk[HD];
    const int tid = threadIdx.x;
    if (tid < HD)
        nq[tid] = fmaxf(sqrtf(g_ssq[bh * HD + tid]), 1e-12f);
    else if (tid < 2 * HD)
        nk[tid - HD] = fmaxf(sqrtf(g_ssq[BATCH * HEADS * HD + bh * HD + (tid - HD)]), 1e-12f);
    __syncthreads();
    const float tv = temp[h];
    {
        int d = tid / HD, e = tid % HD;
        attn[d][e] = g_S[(long)bh * HD * HD + tid] / (nq[d] * nk[e]) * tv;
    }
    __syncthreads();
    if (tid < HD) {
        float m = -1e30f;
        for (int e = 0; e < HD; e++) m = fmaxf(m, attn[tid][e]);
        float sum = 0.f;
        for (int e = 0; e < HD; e++) { float v = expf(attn[tid][e] - m); attn[tid][e] = v; sum += v; }
        float inv = 1.f / sum;
        for (int e = 0; e < HD; e++) attn[tid][e] *= inv;
    }
    __syncthreads();
    // W[b][o][h*24+e] = sum_d proj_w[o][h*24+d] * attn[d][e]
    for (int t = tid; t < CH * HD; t += 576) {
        int o = t / HD, e = t % HD;
        float a = 0.f;
#pragma unroll
        for (int d = 0; d < HD; d++)
            a += proj_w[o * CH + h * HD + d] * attn[d][e];
        g_W[((long)b * CH + o) * CH + h * HD + e] = a;
    }
}

// ---------------- launch ---------------------------------------------------------
extern "C" void kernel_launch(void* const* d_in, const int* in_sizes, int n_in,
                              void* d_out, int out_size)
{
    const float* x      = (const float*)d_in[0];
    const float* qkv_w  = (const float*)d_in[1];
    const float* dw_w   = (const float*)d_in[2];
    const float* proj_w = (const float*)d_in[3];
    const float* temp   = (const float*)d_in[4];
    float* out = (float*)d_out;

    float *p_qkv, *p_dw, *p_W;
    cudaGetSymbolAddress((void**)&p_qkv, g_qkv);
    cudaGetSymbolAddress((void**)&p_dw,  g_dw);
    cudaGetSymbolAddress((void**)&p_W,   g_W);

    zero_kernel<<<72, 256>>>();

    // 1) qkv = qkv_w @ x   : [576x192] @ [192x65536] per batch
    sgemm_kernel<<<dim3(HW / 128, 576 / 64, BATCH), 256>>>(
        qkv_w, 0L, x, (long)CH * HW, p_qkv, 576L * HW, 576, CH);

    // 2) depthwise 3x3
    dwconv_kernel<<<dim3(IMG / 8, 576, BATCH), 256>>>(p_qkv, dw_w);

    // 3) gram + sumsq
    qk_gram_kernel<<<dim3(64, HEADS, BATCH), 288>>>();

    // 4) softmax + fold proj
    combine_kernel<<<BATCH * HEADS, 576>>>(proj_w, temp);

    // 5) out = W[b] @ v : [192x192] @ [192x65536] per batch
    sgemm_kernel<<<dim3(HW / 128, CH / 64, BATCH), 256>>>(
        p_W, (long)CH * CH, p_dw + (long)2 * CH * HW, 576L * HW, out, (long)CH * HW, CH, CH);
}

// round 4
// speedup vs baseline: 1.1262x; 1.1262x over previous
#include <cuda_runtime.h>
#include <cuda_bf16.h>
#include <math.h>
#include <stdint.h>

#define HW   65536
#define IMG  256
#define BATCH 4
#define CH   192
#define HEADS 8
#define HD   24

// ---------------- scratch (device globals; no runtime allocation) ----------------
__device__ float g_qkv[(long)BATCH * 576 * HW];   // after 1x1 conv
__device__ float g_dw [(long)BATCH * 576 * HW];   // after dw 3x3
__device__ float g_S  [BATCH * HEADS * HD * HD];  // raw gram q.k^T
__device__ float g_ssq[2 * BATCH * HEADS * HD];   // sumsq q (first 768), sumsq k
__device__ float g_W  [BATCH * CH * CH];          // proj_w folded with attn

// ---------------- zero accumulators (per-call, graph replay safe) ----------------
__global__ void zero_kernel()
{
    int i = blockIdx.x * blockDim.x + threadIdx.x;
    if (i < BATCH * HEADS * HD * HD) g_S[i] = 0.f;
    if (i < 2 * BATCH * HEADS * HD)  g_ssq[i] = 0.f;
}

// ---------------- tf32 helpers ---------------------------------------------------
__device__ __forceinline__ uint32_t f2tf32(float v)
{
    uint32_t o;
    asm("cvt.rna.tf32.f32 %0, %1;" : "=r"(o) : "f"(v));
    return o;
}

__device__ __forceinline__ void mma_tf32(float* d, const uint32_t* a, const uint32_t* b)
{
    asm volatile(
        "mma.sync.aligned.m16n8k8.row.col.f32.tf32.tf32.f32 "
        "{%0,%1,%2,%3}, {%4,%5,%6,%7}, {%8,%9}, {%0,%1,%2,%3};\n"
        : "+f"(d[0]), "+f"(d[1]), "+f"(d[2]), "+f"(d[3])
        : "r"(a[0]), "r"(a[1]), "r"(a[2]), "r"(a[3]), "r"(b[0]), "r"(b[1]));
}

// ---------------- 3xTF32 GEMM: C[MxHW] = A[MxK] * B[KxHW], batched ---------------
// block tile 64(M) x 128(N) x 16(K), 256 threads, 8 warps as 2(m) x 4(n),
// warp tile 32x32 = 2 m16 tiles x 4 n8 tiles.
__global__ __launch_bounds__(256, 2) void tf32_gemm_kernel(
    const float* __restrict__ A, long aStride,
    const float* __restrict__ B, long bStride,
    float* __restrict__ C, long cStride,
    int M, int K)
{
    const int bz = blockIdx.z;
    const float* Ab = A + (long)bz * aStride;
    const float* Bb = B + (long)bz * bStride;
    float*       Cb = C + (long)bz * cStride;
    const int bm = blockIdx.x * 64;   // grid.x = M tiles (fastest) -> B-tile L2 reuse
    const int bn = blockIdx.y * 128;

    __shared__ uint32_t Ahi[64][20];   // [m][k], stride 20 -> conflict-free frags
    __shared__ uint32_t Alo[64][20];
    __shared__ uint32_t Bhi[16][136];  // [k][n], stride 136 -> conflict-free frags
    __shared__ uint32_t Blo[16][136];

    const int tid  = threadIdx.x;
    const int lane = tid & 31;
    const int wid  = tid >> 5;
    const int warp_m = (wid & 1) * 32;
    const int warp_n = (wid >> 1) * 32;
    const int r  = lane >> 2;     // 0..7
    const int cq = lane & 3;      // 0..3

    const int arow = tid >> 2;          // 0..63
    const int acol = (tid & 3) * 4;     // 0,4,8,12
    const int brow = tid >> 4;          // 0..15
    const int bcol = (tid & 15) * 8;    // 0..120

    float acc[2][4][4];
#pragma unroll
    for (int mi = 0; mi < 2; mi++)
#pragma unroll
        for (int nj = 0; nj < 4; nj++)
#pragma unroll
            for (int i = 0; i < 4; i++) acc[mi][nj][i] = 0.f;

    // stage chunk 0
    float4 aS = *reinterpret_cast<const float4*>(Ab + (long)(bm + arow) * K + acol);
    const float* bp0 = Bb + (long)brow * HW + bn + bcol;
    float4 bS0 = *reinterpret_cast<const float4*>(bp0);
    float4 bS1 = *reinterpret_cast<const float4*>(bp0 + 4);

    for (int k0 = 0; k0 < K; k0 += 16) {
        // convert staged regs to hi/lo tf32 and store to smem
        {
            float av[4] = {aS.x, aS.y, aS.z, aS.w};
#pragma unroll
            for (int i = 0; i < 4; i++) {
                uint32_t h = f2tf32(av[i]);
                Ahi[arow][acol + i] = h;
                Alo[arow][acol + i] = f2tf32(av[i] - __uint_as_float(h));
            }
            float bv[8] = {bS0.x, bS0.y, bS0.z, bS0.w, bS1.x, bS1.y, bS1.z, bS1.w};
#pragma unroll
            for (int i = 0; i < 8; i++) {
                uint32_t h = f2tf32(bv[i]);
                Bhi[brow][bcol + i] = h;
                Blo[brow][bcol + i] = f2tf32(bv[i] - __uint_as_float(h));
            }
        }
        __syncthreads();

        // prefetch next chunk (overlaps with mma below)
        if (k0 + 16 < K) {
            aS = *reinterpret_cast<const float4*>(Ab + (long)(bm + arow) * K + k0 + 16 + acol);
            const float* bp = Bb + (long)(k0 + 16 + brow) * HW + bn + bcol;
            bS0 = *reinterpret_cast<const float4*>(bp);
            bS1 = *reinterpret_cast<const float4*>(bp + 4);
        }

#pragma unroll
        for (int ks = 0; ks < 16; ks += 8) {
            uint32_t ah[2][4], al[2][4], bh[4][2], bl[4][2];
#pragma unroll
            for (int mi = 0; mi < 2; mi++) {
                const int m0 = warp_m + mi * 16;
                ah[mi][0] = Ahi[m0 + r][ks + cq];
                ah[mi][1] = Ahi[m0 + r + 8][ks + cq];
                ah[mi][2] = Ahi[m0 + r][ks + cq + 4];
                ah[mi][3] = Ahi[m0 + r + 8][ks + cq + 4];
                al[mi][0] = Alo[m0 + r][ks + cq];
                al[mi][1] = Alo[m0 + r + 8][ks + cq];
                al[mi][2] = Alo[m0 + r][ks + cq + 4];
                al[mi][3] = Alo[m0 + r + 8][ks + cq + 4];
            }
#pragma unroll
            for (int nj = 0; nj < 4; nj++) {
                const int n0 = warp_n + nj * 8 + r;
                bh[nj][0] = Bhi[ks + cq][n0];
                bh[nj][1] = Bhi[ks + cq + 4][n0];
                bl[nj][0] = Blo[ks + cq][n0];
                bl[nj][1] = Blo[ks + cq + 4][n0];
            }
#pragma unroll
            for (int mi = 0; mi < 2; mi++)
#pragma unroll
                for (int nj = 0; nj < 4; nj++) {
                    mma_tf32(acc[mi][nj], al[mi], bh[nj]);  // Alo*Bhi
                    mma_tf32(acc[mi][nj], ah[mi], bl[nj]);  // Ahi*Blo
                    mma_tf32(acc[mi][nj], ah[mi], bh[nj]);  // Ahi*Bhi
                }
        }
        __syncthreads();
    }

#pragma unroll
    for (int mi = 0; mi < 2; mi++)
#pragma unroll
        for (int nj = 0; nj < 4; nj++) {
            const int row = bm + warp_m + mi * 16 + r;
            const int col = bn + warp_n + nj * 8 + 2 * cq;
            float2 v0 = make_float2(acc[mi][nj][0], acc[mi][nj][1]);
            float2 v1 = make_float2(acc[mi][nj][2], acc[mi][nj][3]);
            *reinterpret_cast<float2*>(Cb + (long)row * HW + col)       = v0;
            *reinterpret_cast<float2*>(Cb + (long)(row + 8) * HW + col) = v1;
        }
}

// ---------------- depthwise 3x3 conv, pad 1, + fused q/k sumsq -------------------
__global__ __launch_bounds__(256) void dwconv_kernel(const float* __restrict__ in,
                                                     const float* __restrict__ w)
{
    const int ch = blockIdx.y;   // 0..575
    const int b  = blockIdx.z;
    const long base = ((long)b * 576 + ch) * HW;
    const float* ip = in + base;
    float* op = g_dw + base;

    float w9[9];
#pragma unroll
    for (int i = 0; i < 9; i++) w9[i] = __ldg(&w[ch * 9 + i]);

    __shared__ float s[10][258];
    const int t = threadIdx.x;          // 0..255 = image column
    const int r0 = blockIdx.x * 8;      // 8 output rows per block
#pragma unroll
    for (int rr = 0; rr < 10; rr++) {
        int r = r0 - 1 + rr;
        s[rr][t + 1] = (r >= 0 && r < IMG) ? ip[r * IMG + t] : 0.f;
    }
    if (t < 10) { s[t][0] = 0.f; s[t][257] = 0.f; }
    __syncthreads();

    float sq = 0.f;
#pragma unroll
    for (int rr = 0; rr < 8; rr++) {
        float acc = 0.f;
#pragma unroll
        for (int ky = 0; ky < 3; ky++)
#pragma unroll
            for (int kx = 0; kx < 3; kx++)
                acc += s[rr + ky][t + kx] * w9[ky * 3 + kx];
        op[(r0 + rr) * IMG + t] = acc;
        sq += acc * acc;
    }

    // fused sumsq for q (ch<192) and k (192<=ch<384) channels
    if (ch < 2 * CH) {
        __shared__ float wsum[8];
#pragma unroll
        for (int off = 16; off > 0; off >>= 1)
            sq += __shfl_xor_sync(0xFFFFFFFFu, sq, off);
        if ((t & 31) == 0) wsum[t >> 5] = sq;
        __syncthreads();
        if (t == 0) {
            float ssum = 0.f;
#pragma unroll
            for (int i = 0; i < 8; i++) ssum += wsum[i];
            int off = (ch < CH) ? (b * CH + ch)
                                : (BATCH * HEADS * HD + b * CH + (ch - CH));
            atomicAdd(&g_ssq[off], ssum);
        }
    }
}

// ---------------- per-(b,h): Sraw = q k^T over HW --------------------------------
__global__ __launch_bounds__(288) void qk_gram_kernel()
{
    const int b = blockIdx.z, h = blockIdx.y;
    const int bh = b * HEADS + h;
    const float* Q  = g_dw + ((long)b * 576 + h * HD) * HW;
    const float* Kp = g_dw + ((long)b * 576 + CH + h * HD) * HW;

    __shared__ float qs[HD][129];
    __shared__ float ks[HD][129];
    __shared__ float red[8 * 576];

    const int tid = threadIdx.x;
    const int g = tid / 36;
    const int p = tid % 36;
    const int d0 = (p % 6) * 4;
    const int e0 = (p / 6) * 4;

    float acc[4][4];
#pragma unroll
    for (int i = 0; i < 4; i++)
#pragma unroll
        for (int j = 0; j < 4; j++) acc[i][j] = 0.f;

    for (int c = 0; c < 8; c++) {
        const long n0 = ((long)blockIdx.x * 8 + c) * 128;
        for (int idx = tid; idx < HD * 128; idx += 288) {
            int r = idx >> 7, cc = idx & 127;
            qs[r][cc] = Q[(long)r * HW + n0 + cc];
            ks[r][cc] = Kp[(long)r * HW + n0 + cc];
        }
        __syncthreads();
        const int nbeg = g * 16;
#pragma unroll 4
        for (int nn = nbeg; nn < nbeg + 16; nn++) {
            float qv[4], kv[4];
#pragma unroll
            for (int i = 0; i < 4; i++) { qv[i] = qs[d0 + i][nn]; kv[i] = ks[e0 + i][nn]; }
#pragma unroll
            for (int i = 0; i < 4; i++)
#pragma unroll
                for (int j = 0; j < 4; j++)
                    acc[i][j] += qv[i] * kv[j];
        }
        __syncthreads();
    }
#pragma unroll
    for (int i = 0; i < 4; i++)
#pragma unroll
        for (int j = 0; j < 4; j++)
            red[g * 576 + p * 16 + i * 4 + j] = acc[i][j];
    __syncthreads();
    for (int t = tid; t < 576; t += 288) {
        float s = 0.f;
#pragma unroll
        for (int gg = 0; gg < 8; gg++) s += red[gg * 576 + t];
        int p2 = t >> 4, idx = t & 15;
        int d = (p2 % 6) * 4 + (idx >> 2);
        int e = (p2 / 6) * 4 + (idx & 3);
        atomicAdd(&g_S[((long)bh * HD + d) * HD + e], s);
    }
}

// ---------------- normalize + softmax + fold attn into proj_w -> W[b] ------------
__global__ __launch_bounds__(576) void combine_kernel(const float* __restrict__ proj_w,
                                                      const float* __restrict__ temp)
{
    const int bh = blockIdx.x;
    const int b = bh >> 3, h = bh & 7;
    __shared__ float attn[HD][HD];
    __shared__ float nq[HD], nk[HD];
    const int tid = threadIdx.x;
    if (tid < HD)
        nq[tid] = fmaxf(sqrtf(g_ssq[bh * HD + tid]), 1e-12f);
    else if (tid < 2 * HD)
        nk[tid - HD] = fmaxf(sqrtf(g_ssq[BATCH * HEADS * HD + bh * HD + (tid - HD)]), 1e-12f);
    __syncthreads();
    const float tv = temp[h];
    {
        int d = tid / HD, e = tid % HD;
        attn[d][e] = g_S[(long)bh * HD * HD + tid] / (nq[d] * nk[e]) * tv;
    }
    __syncthreads();
    if (tid < HD) {
        float m = -1e30f;
        for (int e = 0; e < HD; e++) m = fmaxf(m, attn[tid][e]);
        float sum = 0.f;
        for (int e = 0; e < HD; e++) { float v = expf(attn[tid][e] - m); attn[tid][e] = v; sum += v; }
        float inv = 1.f / sum;
        for (int e = 0; e < HD; e++) attn[tid][e] *= inv;
    }
    __syncthreads();
    for (int t = tid; t < CH * HD; t += 576) {
        int o = t / HD, e = t % HD;
        float a = 0.f;
#pragma unroll
        for (int d = 0; d < HD; d++)
            a += proj_w[o * CH + h * HD + d] * attn[d][e];
        g_W[((long)b * CH + o) * CH + h * HD + e] = a;
    }
}

// ---------------- launch ---------------------------------------------------------
extern "C" void kernel_launch(void* const* d_in, const int* in_sizes, int n_in,
                              void* d_out, int out_size)
{
    const float* x      = (const float*)d_in[0];
    const float* qkv_w  = (const float*)d_in[1];
    const float* dw_w   = (const float*)d_in[2];
    const float* proj_w = (const float*)d_in[3];
    const float* temp   = (const float*)d_in[4];
    float* out = (float*)d_out;

    float *p_qkv, *p_dw, *p_W;
    cudaGetSymbolAddress((void**)&p_qkv, g_qkv);
    cudaGetSymbolAddress((void**)&p_dw,  g_dw);
    cudaGetSymbolAddress((void**)&p_W,   g_W);

    zero_kernel<<<72, 256>>>();

    // 1) qkv = qkv_w @ x : [576x192] @ [192x65536] per batch (tensor cores, 3xTF32)
    tf32_gemm_kernel<<<dim3(576 / 64, HW / 128, BATCH), 256>>>(
        qkv_w, 0L, x, (long)CH * HW, p_qkv, 576L * HW, 576, CH);

    // 2) depthwise 3x3 (+ fused q/k sumsq)
    dwconv_kernel<<<dim3(IMG / 8, 576, BATCH), 256>>>(p_qkv, dw_w);

    // 3) gram
    qk_gram_kernel<<<dim3(64, HEADS, BATCH), 288>>>();

    // 4) softmax + fold proj
    combine_kernel<<<BATCH * HEADS, 576>>>(proj_w, temp);

    // 5) out = W[b] @ v : [192x192] @ [192x65536] per batch (tensor cores, 3xTF32)
    tf32_gemm_kernel<<<dim3(CH / 64, HW / 128, BATCH), 256>>>(
        p_W, (long)CH * CH, p_dw + (long)2 * CH * HW, 576L * HW, out, (long)CH * HW, CH, CH);
}

// round 7
// speedup vs baseline: 2.4279x; 2.1559x over previous
#include <cuda_runtime.h>
#include <cuda_bf16.h>
#include <math.h>
#include <stdint.h>

#define HW    65536
#define IMG   256
#define BATCH 4
#define CH    192
#define HEADS 8
#define HD    24
#define KDIM  192
#define KP    96      // k pairs

// ---------------- scratch (device globals; no runtime allocation) ----------------
__device__ float    g_qkv [(long)BATCH * 576 * HW];   // after 1x1 conv (fp32)
__device__ float    g_dw  [(long)BATCH * 384 * HW];   // q,k after dw conv (fp32)
__device__ uint32_t g_xphi[(long)BATCH * KP * HW];    // x packed bf16 k-pairs, hi
__device__ uint32_t g_xplo[(long)BATCH * KP * HW];    // lo
__device__ uint32_t g_vphi[(long)BATCH * KP * HW];    // v packed bf16 k-pairs, hi
__device__ uint32_t g_vplo[(long)BATCH * KP * HW];
__device__ __nv_bfloat16 g_awhi[576 * KDIM];          // qkv_w bf16 hi
__device__ __nv_bfloat16 g_awlo[576 * KDIM];
__device__ __nv_bfloat16 g_wbhi[BATCH * CH * KDIM];   // folded proj W bf16 hi
__device__ __nv_bfloat16 g_wblo[BATCH * CH * KDIM];
__device__ float g_S  [BATCH * HEADS * HD * HD];
__device__ float g_ssq[2 * BATCH * HEADS * HD];

// ---------------- helpers ---------------------------------------------------------
__device__ __forceinline__ uint32_t pack_bf2(float lo, float hi)
{
    __nv_bfloat162 t = __floats2bfloat162_rn(lo, hi);   // .x -> low 16 bits
    return *reinterpret_cast<uint32_t*>(&t);
}
__device__ __forceinline__ void split1(float v, __nv_bfloat16& h, __nv_bfloat16& l)
{
    h = __float2bfloat16(v);
    l = __float2bfloat16(v - __bfloat162float(h));
}
__device__ __forceinline__ uint32_t smem_u32(const void* p)
{
    uint32_t a;
    asm("{ .reg .u64 t; cvta.to.shared.u64 t, %1; cvt.u32.u64 %0, t; }" : "=r"(a) : "l"(p));
    return a;
}
__device__ __forceinline__ void mma_bf16(float* d, const uint32_t* a, const uint32_t* b)
{
    asm volatile(
        "mma.sync.aligned.m16n8k16.row.col.f32.bf16.bf16.f32 "
        "{%0,%1,%2,%3}, {%4,%5,%6,%7}, {%8,%9}, {%0,%1,%2,%3};\n"
        : "+f"(d[0]), "+f"(d[1]), "+f"(d[2]), "+f"(d[3])
        : "r"(a[0]), "r"(a[1]), "r"(a[2]), "r"(a[3]), "r"(b[0]), "r"(b[1]));
}
#define CP_ASYNC16(saddr, gptr) \
    asm volatile("cp.async.cg.shared.global [%0], [%1], 16;" :: "r"(saddr), "l"(gptr))
#define CP_COMMIT()  asm volatile("cp.async.commit_group;" ::: "memory")
#define CP_WAIT0()   asm volatile("cp.async.wait_group 0;" ::: "memory")
#define CP_WAIT1()   asm volatile("cp.async.wait_group 1;" ::: "memory")

// ---------------- zero accumulators ----------------------------------------------
__global__ void zero_kernel()
{
    int i = blockIdx.x * blockDim.x + threadIdx.x;
    if (i < BATCH * HEADS * HD * HD) g_S[i] = 0.f;
    if (i < 2 * BATCH * HEADS * HD)  g_ssq[i] = 0.f;
}

// ---------------- split x -> packed bf16 k-pair planes ----------------------------
__global__ __launch_bounds__(256) void split_x_kernel(const float* __restrict__ x)
{
    const int n = (blockIdx.x * 256 + threadIdx.x) * 4;
    const int j = blockIdx.y;           // k pair
    const int b = blockIdx.z;
    const float* r0 = x + ((long)b * KDIM + 2 * j) * HW + n;
    float4 v0 = *reinterpret_cast<const float4*>(r0);
    float4 v1 = *reinterpret_cast<const float4*>(r0 + HW);
    float e[4] = {v0.x, v0.y, v0.z, v0.w};
    float o[4] = {v1.x, v1.y, v1.z, v1.w};
    uint4 hi, lo;
    uint32_t* hp = &hi.x; uint32_t* lp = &lo.x;
#pragma unroll
    for (int i = 0; i < 4; i++) {
        __nv_bfloat16 eh, el, oh, ol;
        split1(e[i], eh, el);
        split1(o[i], oh, ol);
        hp[i] = pack_bf2(__bfloat162float(eh) * 0.f + __bfloat162float(eh), __bfloat162float(oh)); // pack eh(lo),oh(hi)
        hp[i] = (uint32_t)*reinterpret_cast<unsigned short*>(&eh) |
                ((uint32_t)*reinterpret_cast<unsigned short*>(&oh) << 16);
        lp[i] = (uint32_t)*reinterpret_cast<unsigned short*>(&el) |
                ((uint32_t)*reinterpret_cast<unsigned short*>(&ol) << 16);
    }
    const long w = ((long)b * KP + j) * HW + n;
    *reinterpret_cast<uint4*>(&g_xphi[w]) = hi;
    *reinterpret_cast<uint4*>(&g_xplo[w]) = lo;
}

// ---------------- split qkv_w -> bf16 hi/lo planes --------------------------------
__global__ void split_aw_kernel(const float* __restrict__ qkv_w)
{
    int i = blockIdx.x * 256 + threadIdx.x;
    if (i < 576 * KDIM) {
        __nv_bfloat16 h, l;
        split1(qkv_w[i], h, l);
        g_awhi[i] = h; g_awlo[i] = l;
    }
}

// ---------------- bf16 split GEMM: C[M x HW] = A[M x 192] * B[192 x HW] ----------
// A: bf16 hi/lo planes row-major [M][192] (k-pairs are natural u32 words)
// B: packed u32 k-pair planes [KP][HW]
// block 64(M) x 128(N), 256 thr, 8 warps (2m x 4n), warp 32x32, k-chunk 16, cp.async x2
__global__ __launch_bounds__(256) void bf16_gemm_kernel(
    const __nv_bfloat16* __restrict__ Ahi, const __nv_bfloat16* __restrict__ Alo, long aStride,
    const uint32_t* __restrict__ Bhi, const uint32_t* __restrict__ Blo,
    float* __restrict__ C, long cStride, int M)
{
    __shared__ uint32_t As[2][2][64][12];   // [buf][hi/lo][m][kpair]  stride 12
    __shared__ uint32_t Bs[2][2][8][132];   // [buf][hi/lo][kpair][n] stride 132

    const int tid  = threadIdx.x;
    const int lane = tid & 31;
    const int wid  = tid >> 5;
    const int bm   = blockIdx.x * 64;
    const long n0  = (long)blockIdx.y * 128;
    const int bz   = blockIdx.z;

    const __nv_bfloat16* Ah = Ahi + (long)bz * aStride;
    const __nv_bfloat16* Al = Alo + (long)bz * aStride;
    const uint32_t* Bh = Bhi + (long)bz * KP * HW;
    const uint32_t* Bl = Blo + (long)bz * KP * HW;
    float* Cb = C + (long)bz * cStride;

    const uint32_t sAs = smem_u32(As);
    const uint32_t sBs = smem_u32(Bs);

    const int warp_m = (wid & 1) * 32;
    const int warp_n = (wid >> 1) * 32;
    const int r  = lane >> 2;
    const int cq = lane & 3;

    float acc[2][4][4];
#pragma unroll
    for (int mt = 0; mt < 2; mt++)
#pragma unroll
        for (int nt = 0; nt < 4; nt++)
#pragma unroll
            for (int i = 0; i < 4; i++) acc[mt][nt][i] = 0.f;

    // ---- chunk loader (cp.async) ----
    auto load_chunk = [&](int c, int bb) {
        if (tid < 128) {                                  // A: 64 rows x 2 halves
            int m = tid >> 1, hf = tid & 1;
            long ge = (long)(bm + m) * KDIM + c * 16 + hf * 8;   // bf16 element idx
            uint32_t da = sAs + (((bb * 2 + 0) * 64 + m) * 12 + hf * 4) * 4;
            CP_ASYNC16(da, (const char*)Ah + ge * 2);
            uint32_t dl = sAs + (((bb * 2 + 1) * 64 + m) * 12 + hf * 4) * 4;
            CP_ASYNC16(dl, (const char*)Al + ge * 2);
        }
        int j = tid >> 5, ln = tid & 31;                  // B: 8 pairs x 128 n
        long gw = ((long)(c * 8 + j)) * HW + n0 + 4 * ln;
        uint32_t db = sBs + (((0 + j) + bb * 16) * 132 + 4 * ln) * 4;          // hi: plane 0
        CP_ASYNC16(db, Bh + gw);
        uint32_t dbl = sBs + (((8 + j) + bb * 16) * 132 + 4 * ln) * 4;         // lo: plane 1
        CP_ASYNC16(dbl, Bl + gw);
    };

    load_chunk(0, 0);
    CP_COMMIT();

    for (int c = 0; c < 12; c++) {
        const int bb = c & 1;
        if (c + 1 < 12) {
            load_chunk(c + 1, bb ^ 1);
            CP_COMMIT();
            CP_WAIT1();
        } else {
            CP_WAIT0();
        }
        __syncthreads();

        uint32_t ah[2][4], al[2][4], bh[4][2], bl[4][2];
#pragma unroll
        for (int mt = 0; mt < 2; mt++) {
            const int m0 = warp_m + mt * 16 + r;
            ah[mt][0] = As[bb][0][m0][cq];
            ah[mt][1] = As[bb][0][m0 + 8][cq];
            ah[mt][2] = As[bb][0][m0][cq + 4];
            ah[mt][3] = As[bb][0][m0 + 8][cq + 4];
            al[mt][0] = As[bb][1][m0][cq];
            al[mt][1] = As[bb][1][m0 + 8][cq];
            al[mt][2] = As[bb][1][m0][cq + 4];
            al[mt][3] = As[bb][1][m0 + 8][cq + 4];
        }
#pragma unroll
        for (int nt = 0; nt < 4; nt++) {
            const int n = warp_n + nt * 8 + r;
            bh[nt][0] = Bs[bb][0][cq][n];
            bh[nt][1] = Bs[bb][0][cq + 4][n];
            bl[nt][0] = Bs[bb][1][cq][n];
            bl[nt][1] = Bs[bb][1][cq + 4][n];
        }
#pragma unroll
        for (int mt = 0; mt < 2; mt++)
#pragma unroll
            for (int nt = 0; nt < 4; nt++) {
                mma_bf16(acc[mt][nt], ah[mt], bh[nt]);
                mma_bf16(acc[mt][nt], ah[mt], bl[nt]);
                mma_bf16(acc[mt][nt], al[mt], bh[nt]);
            }
        __syncthreads();
    }

#pragma unroll
    for (int mt = 0; mt < 2; mt++)
#pragma unroll
        for (int nt = 0; nt < 4; nt++) {
            const int row = bm + warp_m + mt * 16 + r;
            const long col = n0 + warp_n + nt * 8 + 2 * cq;
            *reinterpret_cast<float2*>(Cb + (long)row * HW + col) =
                make_float2(acc[mt][nt][0], acc[mt][nt][1]);
            *reinterpret_cast<float2*>(Cb + (long)(row + 8) * HW + col) =
                make_float2(acc[mt][nt][2], acc[mt][nt][3]);
        }
}

// ---------------- depthwise 3x3: q,k -> fp32 (+sumsq); v -> packed bf16 pairs -----
__global__ __launch_bounds__(256) void dwconv_kernel(const float* __restrict__ in,
                                                     const float* __restrict__ w)
{
    const int y = blockIdx.y;     // 0..383 single q/k channel; 384..479 v pair
    const int b = blockIdx.z;
    const int t = threadIdx.x;
    const int r0 = blockIdx.x * 8;

    __shared__ float s[10][258];

    if (y < 384) {
        const int ch = y;
        const float* ip = in + ((long)b * 576 + ch) * HW;
        float* op = g_dw + ((long)b * 384 + ch) * HW;
        float w9[9];
#pragma unroll
        for (int i = 0; i < 9; i++) w9[i] = __ldg(&w[ch * 9 + i]);
#pragma unroll
        for (int rr = 0; rr < 10; rr++) {
            int rw = r0 - 1 + rr;
            s[rr][t + 1] = (rw >= 0 && rw < IMG) ? ip[rw * IMG + t] : 0.f;
        }
        if (t < 10) { s[t][0] = 0.f; s[t][257] = 0.f; }
        __syncthreads();
        float sq = 0.f;
#pragma unroll
        for (int rr = 0; rr < 8; rr++) {
            float a = 0.f;
#pragma unroll
            for (int ky = 0; ky < 3; ky++)
#pragma unroll
                for (int kx = 0; kx < 3; kx++)
                    a += s[rr + ky][t + kx] * w9[ky * 3 + kx];
            op[(r0 + rr) * IMG + t] = a;
            sq += a * a;
        }
        __shared__ float wsum[8];
#pragma unroll
        for (int off = 16; off > 0; off >>= 1)
            sq += __shfl_xor_sync(0xFFFFFFFFu, sq, off);
        if ((t & 31) == 0) wsum[t >> 5] = sq;
        __syncthreads();
        if (t == 0) {
            float ssum = 0.f;
#pragma unroll
            for (int i = 0; i < 8; i++) ssum += wsum[i];
            int off = (ch < CH) ? (b * CH + ch)
                                : (BATCH * HEADS * HD + b * CH + (ch - CH));
            atomicAdd(&g_ssq[off], ssum);
        }
    } else {
        const int p = y - 384;             // v channel pair
        const int ch0 = 384 + 2 * p;
        float ce[8], co[8];
#pragma unroll
        for (int cc = 0; cc < 2; cc++) {
            const int ch = ch0 + cc;
            const float* ip = in + ((long)b * 576 + ch) * HW;
            float w9[9];
#pragma unroll
            for (int i = 0; i < 9; i++) w9[i] = __ldg(&w[ch * 9 + i]);
            __syncthreads();
#pragma unroll
            for (int rr = 0; rr < 10; rr++) {
                int rw = r0 - 1 + rr;
                s[rr][t + 1] = (rw >= 0 && rw < IMG) ? ip[rw * IMG + t] : 0.f;
            }
            if (t < 10) { s[t][0] = 0.f; s[t][257] = 0.f; }
            __syncthreads();
            float* dst = cc ? co : ce;
#pragma unroll
            for (int rr = 0; rr < 8; rr++) {
                float a = 0.f;
#pragma unroll
                for (int ky = 0; ky < 3; ky++)
#pragma unroll
                    for (int kx = 0; kx < 3; kx++)
                        a += s[rr + ky][t + kx] * w9[ky * 3 + kx];
                dst[rr] = a;
            }
        }
        const long vbase = ((long)b * KP + p) * HW;
#pragma unroll
        for (int rr = 0; rr < 8; rr++) {
            __nv_bfloat16 eh, el, oh, ol;
            split1(ce[rr], eh, el);
            split1(co[rr], oh, ol);
            uint32_t hw_ = (uint32_t)*reinterpret_cast<unsigned short*>(&eh) |
                           ((uint32_t)*reinterpret_cast<unsigned short*>(&oh) << 16);
            uint32_t lw_ = (uint32_t)*reinterpret_cast<unsigned short*>(&el) |
                           ((uint32_t)*reinterpret_cast<unsigned short*>(&ol) << 16);
            g_vphi[vbase + (r0 + rr) * IMG + t] = hw_;
            g_vplo[vbase + (r0 + rr) * IMG + t] = lw_;
        }
    }
}

// ---------------- per-(b,h): Sraw = q k^T over HW --------------------------------
__global__ __launch_bounds__(288) void qk_gram_kernel()
{
    const int b = blockIdx.z, h = blockIdx.y;
    const int bh = b * HEADS + h;
    const float* Q  = g_dw + ((long)b * 384 + h * HD) * HW;
    const float* Kp = g_dw + ((long)b * 384 + CH + h * HD) * HW;

    __shared__ float qs[HD][129];
    __shared__ float ks[HD][129];
    __shared__ float red[8 * 576];

    const int tid = threadIdx.x;
    const int g = tid / 36;
    const int p = tid % 36;
    const int d0 = (p % 6) * 4;
    const int e0 = (p / 6) * 4;

    float acc[4][4];
#pragma unroll
    for (int i = 0; i < 4; i++)
#pragma unroll
        for (int j = 0; j < 4; j++) acc[i][j] = 0.f;

    for (int c = 0; c < 8; c++) {
        const long n0 = ((long)blockIdx.x * 8 + c) * 128;
        for (int idx = tid; idx < HD * 128; idx += 288) {
            int rr = idx >> 7, cc = idx & 127;
            qs[rr][cc] = Q[(long)rr * HW + n0 + cc];
            ks[rr][cc] = Kp[(long)rr * HW + n0 + cc];
        }
        __syncthreads();
        const int nbeg = g * 16;
#pragma unroll 4
        for (int nn = nbeg; nn < nbeg + 16; nn++) {
            float qv[4], kv[4];
#pragma unroll
            for (int i = 0; i < 4; i++) { qv[i] = qs[d0 + i][nn]; kv[i] = ks[e0 + i][nn]; }
#pragma unroll
            for (int i = 0; i < 4; i++)
#pragma unroll
                for (int j = 0; j < 4; j++)
                    acc[i][j] += qv[i] * kv[j];
        }
        __syncthreads();
    }
#pragma unroll
    for (int i = 0; i < 4; i++)
#pragma unroll
        for (int j = 0; j < 4; j++)
            red[g * 576 + p * 16 + i * 4 + j] = acc[i][j];
    __syncthreads();
    for (int t = tid; t < 576; t += 288) {
        float s = 0.f;
#pragma unroll
        for (int gg = 0; gg < 8; gg++) s += red[gg * 576 + t];
        int p2 = t >> 4, idx = t & 15;
        int d = (p2 % 6) * 4 + (idx >> 2);
        int e = (p2 / 6) * 4 + (idx & 3);
        atomicAdd(&g_S[((long)bh * HD + d) * HD + e], s);
    }
}

// ---------------- normalize + softmax + fold attn into proj_w -> bf16 W ----------
__global__ __launch_bounds__(576) void combine_kernel(const float* __restrict__ proj_w,
                                                      const float* __restrict__ temp)
{
    const int bh = blockIdx.x;
    const int b = bh >> 3, h = bh & 7;
    __shared__ float attn[HD][HD];
    __shared__ float nq[HD], nk[HD];
    const int tid = threadIdx.x;
    if (tid < HD)
        nq[tid] = fmaxf(sqrtf(g_ssq[bh * HD + tid]), 1e-12f);
    else if (tid < 2 * HD)
        nk[tid - HD] = fmaxf(sqrtf(g_ssq[BATCH * HEADS * HD + bh * HD + (tid - HD)]), 1e-12f);
    __syncthreads();
    const float tv = temp[h];
    {
        int d = tid / HD, e = tid % HD;
        attn[d][e] = g_S[(long)bh * HD * HD + tid] / (nq[d] * nk[e]) * tv;
    }
    __syncthreads();
    if (tid < HD) {
        float m = -1e30f;
        for (int e = 0; e < HD; e++) m = fmaxf(m, attn[tid][e]);
        float sum = 0.f;
        for (int e = 0; e < HD; e++) { float v = expf(attn[tid][e] - m); attn[tid][e] = v; sum += v; }
        float inv = 1.f / sum;
        for (int e = 0; e < HD; e++) attn[tid][e] *= inv;
    }
    __syncthreads();
    for (int t = tid; t < CH * HD; t += 576) {
        int o = t / HD, e = t % HD;
        float a = 0.f;
#pragma unroll
        for (int d = 0; d < HD; d++)
            a += proj_w[o * CH + h * HD + d] * attn[d][e];
        __nv_bfloat16 hh, ll;
        split1(a, hh, ll);
        long idx = ((long)b * CH + o) * KDIM + h * HD + e;
        g_wbhi[idx] = hh;
        g_wblo[idx] = ll;
    }
}

// ---------------- launch ---------------------------------------------------------
extern "C" void kernel_launch(void* const* d_in, const int* in_sizes, int n_in,
                              void* d_out, int out_size)
{
    const float* x      = (const float*)d_in[0];
    const float* qkv_w  = (const float*)d_in[1];
    const float* dw_w   = (const float*)d_in[2];
    const float* proj_w = (const float*)d_in[3];
    const float* temp   = (const float*)d_in[4];
    float* out = (float*)d_out;

    float *p_qkv;
    __nv_bfloat16 *p_awhi, *p_awlo, *p_wbhi, *p_wblo;
    uint32_t *p_xphi, *p_xplo, *p_vphi, *p_vplo;
    cudaGetSymbolAddress((void**)&p_qkv,  g_qkv);
    cudaGetSymbolAddress((void**)&p_awhi, g_awhi);
    cudaGetSymbolAddress((void**)&p_awlo, g_awlo);
    cudaGetSymbolAddress((void**)&p_wbhi, g_wbhi);
    cudaGetSymbolAddress((void**)&p_wblo, g_wblo);
    cudaGetSymbolAddress((void**)&p_xphi, g_xphi);
    cudaGetSymbolAddress((void**)&p_xplo, g_xplo);
    cudaGetSymbolAddress((void**)&p_vphi, g_vphi);
    cudaGetSymbolAddress((void**)&p_vplo, g_vplo);

    zero_kernel<<<72, 256>>>();
    split_x_kernel<<<dim3(64, KP, BATCH), 256>>>(x);
    split_aw_kernel<<<(576 * KDIM + 255) / 256, 256>>>(qkv_w);

    // 1) qkv = qkv_w @ x  (tensor cores, bf16 3-term split)
    bf16_gemm_kernel<<<dim3(9, HW / 128, BATCH), 256>>>(
        p_awhi, p_awlo, 0L, p_xphi, p_xplo, p_qkv, 576L * HW, 576);

    // 2) depthwise 3x3: q,k fp32 (+sumsq), v -> packed bf16 pairs
    dwconv_kernel<<<dim3(IMG / 8, 480, BATCH), 256>>>(p_qkv, dw_w);

    // 3) gram
    qk_gram_kernel<<<dim3(64, HEADS, BATCH), 288>>>();

    // 4) softmax + fold proj -> bf16 W planes
    combine_kernel<<<BATCH * HEADS, 576>>>(proj_w, temp);

    // 5) out = W[b] @ v  (tensor cores, bf16 3-term split)
    bf16_gemm_kernel<<<dim3(3, HW / 128, BATCH), 256>>>(
        p_wbhi, p_wblo, (long)CH * KDIM, p_vphi, p_vplo, out, (long)CH * HW, CH);
}

// round 8
// speedup vs baseline: 2.7002x; 1.1121x over previous
#include <cuda_runtime.h>
#include <cuda_bf16.h>
#include <math.h>
#include <stdint.h>

#define HW    65536
#define IMG   256
#define BATCH 4
#define CH    192
#define HEADS 8
#define HD    24
#define KDIM  192
#define KP    96      // k pairs
#define KITER 12      // k16 chunks

// ---------------- scratch (device globals; no runtime allocation) ----------------
__device__ float    g_qkv [(long)BATCH * 576 * HW];   // after 1x1 conv (fp32)
__device__ float    g_dw  [(long)BATCH * 384 * HW];   // q,k after dw conv (fp32)
__device__ uint32_t g_xphi[(long)BATCH * KP * HW];    // x packed bf16 k-pairs, hi
__device__ uint32_t g_xplo[(long)BATCH * KP * HW];    // lo
__device__ uint32_t g_vphi[(long)BATCH * KP * HW];    // v packed bf16 k-pairs, hi
__device__ uint32_t g_vplo[(long)BATCH * KP * HW];
__device__ __nv_bfloat16 g_awhi[576 * KDIM];          // qkv_w bf16 hi
__device__ __nv_bfloat16 g_awlo[576 * KDIM];
__device__ __nv_bfloat16 g_wbhi[BATCH * CH * KDIM];   // folded proj W bf16 hi
__device__ __nv_bfloat16 g_wblo[BATCH * CH * KDIM];
__device__ float g_S  [BATCH * HEADS * HD * HD];
__device__ float g_ssq[2 * BATCH * HEADS * HD];

// ---------------- helpers ---------------------------------------------------------
__device__ __forceinline__ void split1(float v, __nv_bfloat16& h, __nv_bfloat16& l)
{
    h = __float2bfloat16(v);
    l = __float2bfloat16(v - __bfloat162float(h));
}
__device__ __forceinline__ uint32_t smem_u32(const void* p)
{
    uint32_t a;
    asm("{ .reg .u64 t; cvta.to.shared.u64 t, %1; cvt.u32.u64 %0, t; }" : "=r"(a) : "l"(p));
    return a;
}
__device__ __forceinline__ void mma_bf16(float* d, const uint32_t* a, const uint32_t* b)
{
    asm volatile(
        "mma.sync.aligned.m16n8k16.row.col.f32.bf16.bf16.f32 "
        "{%0,%1,%2,%3}, {%4,%5,%6,%7}, {%8,%9}, {%0,%1,%2,%3};\n"
        : "+f"(d[0]), "+f"(d[1]), "+f"(d[2]), "+f"(d[3])
        : "r"(a[0]), "r"(a[1]), "r"(a[2]), "r"(a[3]), "r"(b[0]), "r"(b[1]));
}
#define CP_ASYNC16(saddr, gptr) \
    asm volatile("cp.async.cg.shared.global [%0], [%1], 16;" :: "r"(saddr), "l"(gptr))
#define CP_COMMIT()  asm volatile("cp.async.commit_group;" ::: "memory")
#define CP_WAIT0()   asm volatile("cp.async.wait_group 0;" ::: "memory")
#define CP_WAIT1()   asm volatile("cp.async.wait_group 1;" ::: "memory")

// ---------------- zero accumulators ----------------------------------------------
__global__ void zero_kernel()
{
    int i = blockIdx.x * blockDim.x + threadIdx.x;
    if (i < BATCH * HEADS * HD * HD) g_S[i] = 0.f;
    if (i < 2 * BATCH * HEADS * HD)  g_ssq[i] = 0.f;
}

// ---------------- split x -> packed bf16 k-pair planes ----------------------------
__global__ __launch_bounds__(256) void split_x_kernel(const float* __restrict__ x)
{
    const int n = (blockIdx.x * 256 + threadIdx.x) * 4;
    const int j = blockIdx.y;           // k pair
    const int b = blockIdx.z;
    const float* r0 = x + ((long)b * KDIM + 2 * j) * HW + n;
    float4 v0 = *reinterpret_cast<const float4*>(r0);
    float4 v1 = *reinterpret_cast<const float4*>(r0 + HW);
    float e[4] = {v0.x, v0.y, v0.z, v0.w};
    float o[4] = {v1.x, v1.y, v1.z, v1.w};
    uint4 hi, lo;
    uint32_t* hp = &hi.x; uint32_t* lp = &lo.x;
#pragma unroll
    for (int i = 0; i < 4; i++) {
        __nv_bfloat16 eh, el, oh, ol;
        split1(e[i], eh, el);
        split1(o[i], oh, ol);
        hp[i] = (uint32_t)*reinterpret_cast<unsigned short*>(&eh) |
                ((uint32_t)*reinterpret_cast<unsigned short*>(&oh) << 16);
        lp[i] = (uint32_t)*reinterpret_cast<unsigned short*>(&el) |
                ((uint32_t)*reinterpret_cast<unsigned short*>(&ol) << 16);
    }
    const long w = ((long)b * KP + j) * HW + n;
    *reinterpret_cast<uint4*>(&g_xphi[w]) = hi;
    *reinterpret_cast<uint4*>(&g_xplo[w]) = lo;
}

// ---------------- split qkv_w -> bf16 hi/lo planes --------------------------------
__global__ void split_aw_kernel(const float* __restrict__ qkv_w)
{
    int i = blockIdx.x * 256 + threadIdx.x;
    if (i < 576 * KDIM) {
        __nv_bfloat16 h, l;
        split1(qkv_w[i], h, l);
        g_awhi[i] = h; g_awlo[i] = l;
    }
}

// ---------------- bf16 split GEMM: C[M x HW] = A[M x 192] * B[192 x HW] ----------
// 3-stage cp.async pipeline, 1 barrier per k16 chunk, term-major MMA order.
// block 64(M) x 128(N), 256 thr, 8 warps (2m x 4n), warp 32x32.
__global__ __launch_bounds__(256) void bf16_gemm_kernel(
    const __nv_bfloat16* __restrict__ Ahi, const __nv_bfloat16* __restrict__ Alo, long aStride,
    const uint32_t* __restrict__ Bhi, const uint32_t* __restrict__ Blo,
    float* __restrict__ C, long cStride, int M)
{
    __shared__ uint32_t As[3][2][64][12];   // [stage][hi/lo][m][kpair]  stride 12 (conflict-free)
    __shared__ uint32_t Bs[3][2][8][136];   // [stage][hi/lo][kpair][n] stride 136 (conflict-free)

    const int tid  = threadIdx.x;
    const int lane = tid & 31;
    const int wid  = tid >> 5;
    const int bm   = blockIdx.x * 64;
    const long n0  = (long)blockIdx.y * 128;
    const int bz   = blockIdx.z;

    const __nv_bfloat16* Ah = Ahi + (long)bz * aStride;
    const __nv_bfloat16* Al = Alo + (long)bz * aStride;
    const uint32_t* Bh = Bhi + (long)bz * KP * HW;
    const uint32_t* Bl = Blo + (long)bz * KP * HW;
    float* Cb = C + (long)bz * cStride;

    const uint32_t sAs = smem_u32(As);
    const uint32_t sBs = smem_u32(Bs);

    const int warp_m = (wid & 1) * 32;
    const int warp_n = (wid >> 1) * 32;
    const int r  = lane >> 2;
    const int cq = lane & 3;

    float acc[2][4][4];
#pragma unroll
    for (int mt = 0; mt < 2; mt++)
#pragma unroll
        for (int nt = 0; nt < 4; nt++)
#pragma unroll
            for (int i = 0; i < 4; i++) acc[mt][nt][i] = 0.f;

    auto load_chunk = [&](int c, int st) {
        if (tid < 128) {                                  // A: 64 rows x 2 halves
            int m = tid >> 1, hf = tid & 1;
            long ge = (long)(bm + m) * KDIM + c * 16 + hf * 8;   // bf16 element idx
            uint32_t da = sAs + (((st * 2 + 0) * 64 + m) * 12 + hf * 4) * 4;
            CP_ASYNC16(da, (const char*)Ah + ge * 2);
            uint32_t dl = sAs + (((st * 2 + 1) * 64 + m) * 12 + hf * 4) * 4;
            CP_ASYNC16(dl, (const char*)Al + ge * 2);
        }
        int j = tid >> 5, ln = tid & 31;                  // B: 8 kpairs x 128 n
        long gw = ((long)(c * 8 + j)) * HW + n0 + 4 * ln;
        uint32_t db  = sBs + (((st * 2 + 0) * 8 + j) * 136 + 4 * ln) * 4;
        CP_ASYNC16(db, Bh + gw);
        uint32_t dbl = sBs + (((st * 2 + 1) * 8 + j) * 136 + 4 * ln) * 4;
        CP_ASYNC16(dbl, Bl + gw);
    };

    load_chunk(0, 0); CP_COMMIT();
    load_chunk(1, 1); CP_COMMIT();

    for (int c = 0; c < KITER; c++) {
        const int st = c % 3;
        if (c == KITER - 1) { CP_WAIT0(); } else { CP_WAIT1(); }
        __syncthreads();

        // frag loads
        uint32_t ah[2][4], al[2][4], bh[4][2], bl[4][2];
#pragma unroll
        for (int mt = 0; mt < 2; mt++) {
            const int m0 = warp_m + mt * 16 + r;
            ah[mt][0] = As[st][0][m0][cq];
            ah[mt][1] = As[st][0][m0 + 8][cq];
            ah[mt][2] = As[st][0][m0][cq + 4];
            ah[mt][3] = As[st][0][m0 + 8][cq + 4];
            al[mt][0] = As[st][1][m0][cq];
            al[mt][1] = As[st][1][m0 + 8][cq];
            al[mt][2] = As[st][1][m0][cq + 4];
            al[mt][3] = As[st][1][m0 + 8][cq + 4];
        }
#pragma unroll
        for (int nt = 0; nt < 4; nt++) {
            const int n = warp_n + nt * 8 + r;
            bh[nt][0] = Bs[st][0][cq][n];
            bh[nt][1] = Bs[st][0][cq + 4][n];
            bl[nt][0] = Bs[st][1][cq][n];
            bl[nt][1] = Bs[st][1][cq + 4][n];
        }

        // prefetch stage c+2 (after frags consumed the barrier-protected data)
        if (c + 2 < KITER) {
            load_chunk(c + 2, (c + 2) % 3);
            CP_COMMIT();
        }

        // term-major MMA: 8 independent MMAs between accumulator reuses
#pragma unroll
        for (int mt = 0; mt < 2; mt++)
#pragma unroll
            for (int nt = 0; nt < 4; nt++)
                mma_bf16(acc[mt][nt], ah[mt], bh[nt]);
#pragma unroll
        for (int mt = 0; mt < 2; mt++)
#pragma unroll
            for (int nt = 0; nt < 4; nt++)
                mma_bf16(acc[mt][nt], ah[mt], bl[nt]);
#pragma unroll
        for (int mt = 0; mt < 2; mt++)
#pragma unroll
            for (int nt = 0; nt < 4; nt++)
                mma_bf16(acc[mt][nt], al[mt], bh[nt]);
    }

#pragma unroll
    for (int mt = 0; mt < 2; mt++)
#pragma unroll
        for (int nt = 0; nt < 4; nt++) {
            const int row = bm + warp_m + mt * 16 + r;
            const long col = n0 + warp_n + nt * 8 + 2 * cq;
            *reinterpret_cast<float2*>(Cb + (long)row * HW + col) =
                make_float2(acc[mt][nt][0], acc[mt][nt][1]);
            *reinterpret_cast<float2*>(Cb + (long)(row + 8) * HW + col) =
                make_float2(acc[mt][nt][2], acc[mt][nt][3]);
        }
}

// ---------------- depthwise 3x3: q,k -> fp32 (+sumsq); v -> packed bf16 pairs -----
__global__ __launch_bounds__(256) void dwconv_kernel(const float* __restrict__ in,
                                                     const float* __restrict__ w)
{
    const int y = blockIdx.y;     // 0..383 single q/k channel; 384..479 v pair
    const int b = blockIdx.z;
    const int t = threadIdx.x;
    const int r0 = blockIdx.x * 8;

    __shared__ float s[10][258];

    if (y < 384) {
        const int ch = y;
        const float* ip = in + ((long)b * 576 + ch) * HW;
        float* op = g_dw + ((long)b * 384 + ch) * HW;
        float w9[9];
#pragma unroll
        for (int i = 0; i < 9; i++) w9[i] = __ldg(&w[ch * 9 + i]);
#pragma unroll
        for (int rr = 0; rr < 10; rr++) {
            int rw = r0 - 1 + rr;
            s[rr][t + 1] = (rw >= 0 && rw < IMG) ? ip[rw * IMG + t] : 0.f;
        }
        if (t < 10) { s[t][0] = 0.f; s[t][257] = 0.f; }
        __syncthreads();
        float sq = 0.f;
#pragma unroll
        for (int rr = 0; rr < 8; rr++) {
            float a = 0.f;
#pragma unroll
            for (int ky = 0; ky < 3; ky++)
#pragma unroll
                for (int kx = 0; kx < 3; kx++)
                    a += s[rr + ky][t + kx] * w9[ky * 3 + kx];
            op[(r0 + rr) * IMG + t] = a;
            sq += a * a;
        }
        __shared__ float wsum[8];
#pragma unroll
        for (int off = 16; off > 0; off >>= 1)
            sq += __shfl_xor_sync(0xFFFFFFFFu, sq, off);
        if ((t & 31) == 0) wsum[t >> 5] = sq;
        __syncthreads();
        if (t == 0) {
            float ssum = 0.f;
#pragma unroll
            for (int i = 0; i < 8; i++) ssum += wsum[i];
            int off = (ch < CH) ? (b * CH + ch)
                                : (BATCH * HEADS * HD + b * CH + (ch - CH));
            atomicAdd(&g_ssq[off], ssum);
        }
    } else {
        const int p = y - 384;             // v channel pair
        const int ch0 = 384 + 2 * p;
        float ce[8], co[8];
#pragma unroll
        for (int cc = 0; cc < 2; cc++) {
            const int ch = ch0 + cc;
            const float* ip = in + ((long)b * 576 + ch) * HW;
            float w9[9];
#pragma unroll
            for (int i = 0; i < 9; i++) w9[i] = __ldg(&w[ch * 9 + i]);
            __syncthreads();
#pragma unroll
            for (int rr = 0; rr < 10; rr++) {
                int rw = r0 - 1 + rr;
                s[rr][t + 1] = (rw >= 0 && rw < IMG) ? ip[rw * IMG + t] : 0.f;
            }
            if (t < 10) { s[t][0] = 0.f; s[t][257] = 0.f; }
            __syncthreads();
            float* dst = cc ? co : ce;
#pragma unroll
            for (int rr = 0; rr < 8; rr++) {
                float a = 0.f;
#pragma unroll
                for (int ky = 0; ky < 3; ky++)
#pragma unroll
                    for (int kx = 0; kx < 3; kx++)
                        a += s[rr + ky][t + kx] * w9[ky * 3 + kx];
                dst[rr] = a;
            }
        }
        const long vbase = ((long)b * KP + p) * HW;
#pragma unroll
        for (int rr = 0; rr < 8; rr++) {
            __nv_bfloat16 eh, el, oh, ol;
            split1(ce[rr], eh, el);
            split1(co[rr], oh, ol);
            uint32_t hw_ = (uint32_t)*reinterpret_cast<unsigned short*>(&eh) |
                           ((uint32_t)*reinterpret_cast<unsigned short*>(&oh) << 16);
            uint32_t lw_ = (uint32_t)*reinterpret_cast<unsigned short*>(&el) |
                           ((uint32_t)*reinterpret_cast<unsigned short*>(&ol) << 16);
            g_vphi[vbase + (r0 + rr) * IMG + t] = hw_;
            g_vplo[vbase + (r0 + rr) * IMG + t] = lw_;
        }
    }
}

// ---------------- per-(b,h): Sraw = q k^T over HW (float4 inner loop) ------------
__global__ __launch_bounds__(288) void qk_gram_kernel()
{
    const int b = blockIdx.z, h = blockIdx.y;
    const int bh = b * HEADS + h;
    const float* Q  = g_dw + ((long)b * 384 + h * HD) * HW;
    const float* Kp = g_dw + ((long)b * 384 + CH + h * HD) * HW;

    __shared__ float qs[HD][132];
    __shared__ float ks[HD][132];
    __shared__ float red[8 * 576];

    const int tid = threadIdx.x;
    const int g = tid / 36;
    const int p = tid % 36;
    const int d0 = (p % 6) * 4;
    const int e0 = (p / 6) * 4;

    float acc[4][4];
#pragma unroll
    for (int i = 0; i < 4; i++)
#pragma unroll
        for (int j = 0; j < 4; j++) acc[i][j] = 0.f;

    for (int c = 0; c < 8; c++) {
        const long n0 = ((long)blockIdx.x * 8 + c) * 128;
        for (int idx = tid; idx < HD * 32; idx += 288) {
            int rr = idx >> 5, cc = (idx & 31) << 2;
            *reinterpret_cast<float4*>(&qs[rr][cc]) =
                *reinterpret_cast<const float4*>(Q + (long)rr * HW + n0 + cc);
            *reinterpret_cast<float4*>(&ks[rr][cc]) =
                *reinterpret_cast<const float4*>(Kp + (long)rr * HW + n0 + cc);
        }
        __syncthreads();
        const int nbeg = g * 16;
#pragma unroll
        for (int nn = nbeg; nn < nbeg + 16; nn += 4) {
            float4 qv[4], kv[4];
#pragma unroll
            for (int i = 0; i < 4; i++) {
                qv[i] = *reinterpret_cast<const float4*>(&qs[d0 + i][nn]);
                kv[i] = *reinterpret_cast<const float4*>(&ks[e0 + i][nn]);
            }
#pragma unroll
            for (int i = 0; i < 4; i++)
#pragma unroll
                for (int j = 0; j < 4; j++)
                    acc[i][j] += qv[i].x * kv[j].x + qv[i].y * kv[j].y
                               + qv[i].z * kv[j].z + qv[i].w * kv[j].w;
        }
        __syncthreads();
    }
#pragma unroll
    for (int i = 0; i < 4; i++)
#pragma unroll
        for (int j = 0; j < 4; j++)
            red[g * 576 + p * 16 + i * 4 + j] = acc[i][j];
    __syncthreads();
    for (int t = tid; t < 576; t += 288) {
        float s = 0.f;
#pragma unroll
        for (int gg = 0; gg < 8; gg++) s += red[gg * 576 + t];
        int p2 = t >> 4, idx = t & 15;
        int d = (p2 % 6) * 4 + (idx >> 2);
        int e = (p2 / 6) * 4 + (idx & 3);
        atomicAdd(&g_S[((long)bh * HD + d) * HD + e], s);
    }
}

// ---------------- normalize + softmax + fold attn into proj_w -> bf16 W ----------
__global__ __launch_bounds__(576) void combine_kernel(const float* __restrict__ proj_w,
                                                      const float* __restrict__ temp)
{
    const int bh = blockIdx.x;
    const int b = bh >> 3, h = bh & 7;
    __shared__ float attn[HD][HD];
    __shared__ float nq[HD], nk[HD];
    const int tid = threadIdx.x;
    if (tid < HD)
        nq[tid] = fmaxf(sqrtf(g_ssq[bh * HD + tid]), 1e-12f);
    else if (tid < 2 * HD)
        nk[tid - HD] = fmaxf(sqrtf(g_ssq[BATCH * HEADS * HD + bh * HD + (tid - HD)]), 1e-12f);
    __syncthreads();
    const float tv = temp[h];
    {
        int d = tid / HD, e = tid % HD;
        attn[d][e] = g_S[(long)bh * HD * HD + tid] / (nq[d] * nk[e]) * tv;
    }
    __syncthreads();
    if (tid < HD) {
        float m = -1e30f;
        for (int e = 0; e < HD; e++) m = fmaxf(m, attn[tid][e]);
        float sum = 0.f;
        for (int e = 0; e < HD; e++) { float v = expf(attn[tid][e] - m); attn[tid][e] = v; sum += v; }
        float inv = 1.f / sum;
        for (int e = 0; e < HD; e++) attn[tid][e] *= inv;
    }
    __syncthreads();
    for (int t = tid; t < CH * HD; t += 576) {
        int o = t / HD, e = t % HD;
        float a = 0.f;
#pragma unroll
        for (int d = 0; d < HD; d++)
            a += proj_w[o * CH + h * HD + d] * attn[d][e];
        __nv_bfloat16 hh, ll;
        split1(a, hh, ll);
        long idx = ((long)b * CH + o) * KDIM + h * HD + e;
        g_wbhi[idx] = hh;
        g_wblo[idx] = ll;
    }
}

// ---------------- launch ---------------------------------------------------------
extern "C" void kernel_launch(void* const* d_in, const int* in_sizes, int n_in,
                              void* d_out, int out_size)
{
    const float* x      = (const float*)d_in[0];
    const float* qkv_w  = (const float*)d_in[1];
    const float* dw_w   = (const float*)d_in[2];
    const float* proj_w = (const float*)d_in[3];
    const float* temp   = (const float*)d_in[4];
    float* out = (float*)d_out;

    float *p_qkv;
    __nv_bfloat16 *p_awhi, *p_awlo, *p_wbhi, *p_wblo;
    uint32_t *p_xphi, *p_xplo, *p_vphi, *p_vplo;
    cudaGetSymbolAddress((void**)&p_qkv,  g_qkv);
    cudaGetSymbolAddress((void**)&p_awhi, g_awhi);
    cudaGetSymbolAddress((void**)&p_awlo, g_awlo);
    cudaGetSymbolAddress((void**)&p_wbhi, g_wbhi);
    cudaGetSymbolAddress((void**)&p_wblo, g_wblo);
    cudaGetSymbolAddress((void**)&p_xphi, g_xphi);
    cudaGetSymbolAddress((void**)&p_xplo, g_xplo);
    cudaGetSymbolAddress((void**)&p_vphi, g_vphi);
    cudaGetSymbolAddress((void**)&p_vplo, g_vplo);

    zero_kernel<<<72, 256>>>();
    split_x_kernel<<<dim3(64, KP, BATCH), 256>>>(x);
    split_aw_kernel<<<(576 * KDIM + 255) / 256, 256>>>(qkv_w);

    // 1) qkv = qkv_w @ x  (tensor cores, bf16 3-term split)
    bf16_gemm_kernel<<<dim3(9, HW / 128, BATCH), 256>>>(
        p_awhi, p_awlo, 0L, p_xphi, p_xplo, p_qkv, 576L * HW, 576);

    // 2) depthwise 3x3: q,k fp32 (+sumsq), v -> packed bf16 pairs
    dwconv_kernel<<<dim3(IMG / 8, 480, BATCH), 256>>>(p_qkv, dw_w);

    // 3) gram
    qk_gram_kernel<<<dim3(64, HEADS, BATCH), 288>>>();

    // 4) softmax + fold proj -> bf16 W planes
    combine_kernel<<<BATCH * HEADS, 576>>>(proj_w, temp);

    // 5) out = W[b] @ v  (tensor cores, bf16 3-term split)
    bf16_gemm_kernel<<<dim3(3, HW / 128, BATCH), 256>>>(
        p_wbhi, p_wblo, (long)CH * KDIM, p_vphi, p_vplo, out, (long)CH * HW, CH);
}